// round 10
// baseline (speedup 1.0000x reference)
#include <cuda_runtime.h>
#include <cuda_bf16.h>

// Zim_67430986547716 — bbox mask + Gaussian point mask.
// R10: cut total issued warp-slots ~40% vs R8. Each thread owns 1 row x 8 cols:
// per point = 1 LDS.32 (dy2 dup) + 1 LDS.128 (4 dx2 u16-pairs) + 4 VIADDMNMX
// = 6 slots per 8 pixels (0.75 slots/point-pixel vs 1.0 in R8).
// Grid (256,2) x 256 thr = 4096 warps, single wave at 4 blocks/SM.
// Tropical trick unchanged: max_p exp(-d2/882) = exp(-min_p d2/882);
// invalid points carry +30000 bias (exp -> exactly 0).

#define MASK_N 64
#define NPTS   32
#define INV_STRIDE (1.0f / 16.0f)
#define INV_2SIG2  (1.0f / 882.0f)   // 2*21*21

__global__ __launch_bounds__(256, 4)
void zim_masks_kernel(const float* __restrict__ boxes,
                      const float* __restrict__ pts,
                      float* __restrict__ bbox_out,
                      float* __restrict__ point_out)
{
    __shared__ unsigned int sdx2p[NPTS * 32];  // 4KB: [p][cpair] dx2 u16 pairs, all 64 cols
    __shared__ unsigned int sdy2d[NPTS * 32];  // 4KB: [p][row] (dy2+bias) dup u16x2, 32 rows

    const int b      = blockIdx.x;
    const int sub    = blockIdx.y;              // 0: rows 0-31, 1: rows 32-63
    const int i_base = sub << 5;
    const int tid    = threadIdx.x;

    // ---- bbox bounds (uniform; L1 broadcast, parallel in all threads) ----
    const float x0 = boxes[b * 4 + 0];
    const float y0 = boxes[b * 4 + 1];
    const float x1 = boxes[b * 4 + 2];
    const float y1 = boxes[b * 4 + 3];
    const int xmin_i = max((int)floorf(fminf(x0, x1) * INV_STRIDE), 0);
    const int ymin_i = max((int)floorf(fminf(y0, y1) * INV_STRIDE), 0);
    const int xmax_i = min((int)floorf(fmaxf(x0, x1) * INV_STRIDE) + 1, MASK_N);
    const int ymax_i = min((int)floorf(fmaxf(y0, y1) * INV_STRIDE) + 1, MASK_N);

    // ---- build u16 distance tables (4 iters each, R8-style parallel prologue) ----
    #pragma unroll
    for (int k = tid; k < NPTS * 32; k += 256) {        // dx2 pairs: all 64 cols
        const int p = k >> 5;
        const float x = __ldg(&pts[(b * NPTS + p) * 2 + 0]);
        const int px = (int)floorf(x * INV_STRIDE);
        const int c0 = (k & 31) << 1;
        const int d0 = c0 - px;
        const int d1 = d0 + 1;
        sdx2p[k] = (unsigned int)(d0 * d0) | ((unsigned int)(d1 * d1) << 16);
    }
    #pragma unroll
    for (int k = tid; k < NPTS * 32; k += 256) {        // dy2+bias duplicated
        const int p = k >> 5;
        const float x = __ldg(&pts[(b * NPTS + p) * 2 + 0]);
        const float y = __ldg(&pts[(b * NPTS + p) * 2 + 1]);
        const int px = (int)floorf(x * INV_STRIDE);
        const int py = (int)floorf(y * INV_STRIDE);
        const bool valid = (px >= 0) & (py >= 0) & (px < MASK_N) & (py < MASK_N);
        const int d = i_base + (k & 31) - py;
        const unsigned int v = (unsigned int)(d * d + (valid ? 0 : 30000));
        sdy2d[k] = v | (v << 16);
    }
    __syncthreads();

    // ---- per-thread: 1 row x 8 cols, u16x2 SIMD min over 32 points ----
    const int il = tid >> 3;            // 0..31 local row
    const int cg = tid & 7;             // col group: cols 8*cg .. 8*cg+7

    unsigned int m01 = 0xFFFFFFFFu, m23 = 0xFFFFFFFFu;
    unsigned int m45 = 0xFFFFFFFFu, m67 = 0xFFFFFFFFu;

    const unsigned int* dyp = &sdy2d[il];
    const unsigned int* dxp = &sdx2p[cg * 4];

    #pragma unroll 4
    for (int p = 0; p < NPTS; p++) {
        const unsigned int dyd = dyp[p * 32];
        const uint4 dx = *reinterpret_cast<const uint4*>(dxp + p * 32);
        m01 = __viaddmin_u16x2(dyd, dx.x, m01);
        m23 = __viaddmin_u16x2(dyd, dx.y, m23);
        m45 = __viaddmin_u16x2(dyd, dx.z, m45);
        m67 = __viaddmin_u16x2(dyd, dx.w, m67);
    }

    // ---- one exp per pixel (8) ----
    const float g0 = __expf((float)(m01 & 0xFFFFu) * -INV_2SIG2);
    const float g1 = __expf((float)(m01 >> 16)     * -INV_2SIG2);
    const float g2 = __expf((float)(m23 & 0xFFFFu) * -INV_2SIG2);
    const float g3 = __expf((float)(m23 >> 16)     * -INV_2SIG2);
    const float g4 = __expf((float)(m45 & 0xFFFFu) * -INV_2SIG2);
    const float g5 = __expf((float)(m45 >> 16)     * -INV_2SIG2);
    const float g6 = __expf((float)(m67 & 0xFFFFu) * -INV_2SIG2);
    const float g7 = __expf((float)(m67 >> 16)     * -INV_2SIG2);

    // ---- stores: 2x float4 per output ----
    const int i = i_base + il;
    const int j = cg << 3;
    const size_t base = (size_t)b * (MASK_N * MASK_N) + (size_t)i * MASK_N + j;

    float4* pout = reinterpret_cast<float4*>(point_out + base);
    pout[0] = make_float4(g0, g1, g2, g3);
    pout[1] = make_float4(g4, g5, g6, g7);

    const bool inY = (i >= ymin_i) & (i < ymax_i);
    float4 bv0, bv1;
    bv0.x = (inY & (j + 0 >= xmin_i) & (j + 0 < xmax_i)) ? 1.f : 0.f;
    bv0.y = (inY & (j + 1 >= xmin_i) & (j + 1 < xmax_i)) ? 1.f : 0.f;
    bv0.z = (inY & (j + 2 >= xmin_i) & (j + 2 < xmax_i)) ? 1.f : 0.f;
    bv0.w = (inY & (j + 3 >= xmin_i) & (j + 3 < xmax_i)) ? 1.f : 0.f;
    bv1.x = (inY & (j + 4 >= xmin_i) & (j + 4 < xmax_i)) ? 1.f : 0.f;
    bv1.y = (inY & (j + 5 >= xmin_i) & (j + 5 < xmax_i)) ? 1.f : 0.f;
    bv1.z = (inY & (j + 6 >= xmin_i) & (j + 6 < xmax_i)) ? 1.f : 0.f;
    bv1.w = (inY & (j + 7 >= xmin_i) & (j + 7 < xmax_i)) ? 1.f : 0.f;
    float4* bout = reinterpret_cast<float4*>(bbox_out + base);
    bout[0] = bv0;
    bout[1] = bv1;
}

extern "C" void kernel_launch(void* const* d_in, const int* in_sizes, int n_in,
                              void* d_out, int out_size) {
    const float* boxes = (const float*)d_in[0];   // 256*4
    const float* pts   = (const float*)d_in[1];   // 256*32*2
    float* out = (float*)d_out;                   // 2 * 256*64*64
    const int B = in_sizes[0] / 4;                // 256
    float* bbox_out  = out;
    float* point_out = out + (size_t)B * MASK_N * MASK_N;
    dim3 grid(B, 2);
    zim_masks_kernel<<<grid, 256>>>(boxes, pts, bbox_out, point_out);
}

// round 11
// speedup vs baseline: 1.0108x; 1.0108x over previous
#include <cuda_runtime.h>
#include <cuda_bf16.h>

// Zim_67430986547716 — bbox mask + Gaussian point mask.
// R11: R8 shape (1024 quadrant blocks x 256 thr, 8192 warps, single wave,
// tropical u16 min + exp-at-end) with both phases slimmed:
//  - prologue: each thread loads its point ONCE (coalesced float2, 8-way
//    broadcast), writes its own table share: 2 LDG total (pts + boxes float4)
//  - tables point-major + padded strides: main loop = 3 LDS.128 + 8 VIADDMNMX
//    per 4 points (11 slots/16 pt-px, bank-conflict-free)

#define MASK_N 64
#define NPTS   32
#define INV_STRIDE (1.0f / 16.0f)
#define INV_2SIG2  (1.0f / 882.0f)   // 2*21*21

#define DY_STRIDE 36   // words per row (pad 4): (il*4 + p) bank starts disjoint
#define DX_STRIDE 34   // uint2 per cg  (pad 2): (cg*4 + 2p) bank starts disjoint

__global__ __launch_bounds__(256, 8)
void zim_masks_kernel(const float* __restrict__ boxes,
                      const float* __restrict__ pts,
                      float* __restrict__ bbox_out,
                      float* __restrict__ point_out)
{
    __shared__ __align__(16) unsigned int sdy[32 * DY_STRIDE]; // [row][p] (dy2+bias) dup u16x2
    __shared__ __align__(16) uint2        sdx[8 * DX_STRIDE];  // [cg][p] 2 u16 dx2-pairs (4 cols)

    const int b      = blockIdx.x;
    const int quad   = blockIdx.y;              // 0..3
    const int i_base = (quad >> 1) << 5;        // 0 or 32
    const int j_base = (quad & 1) << 5;         // 0 or 32
    const int tid    = threadIdx.x;

    // ---- bbox bounds: single LDG.128, uniform ----
    const float4 bx = __ldg(&reinterpret_cast<const float4*>(boxes)[b]);
    const int xmin_i = max((int)floorf(fminf(bx.x, bx.z) * INV_STRIDE), 0);
    const int ymin_i = max((int)floorf(fminf(bx.y, bx.w) * INV_STRIDE), 0);
    const int xmax_i = min((int)floorf(fmaxf(bx.x, bx.z) * INV_STRIDE) + 1, MASK_N);
    const int ymax_i = min((int)floorf(fmaxf(bx.y, bx.w) * INV_STRIDE) + 1, MASK_N);

    // ---- prologue: thread (p, g) loads point p once, writes its table share ----
    {
        const int p = tid & 31;                 // point index
        const int g = tid >> 5;                 // group 0..7
        const float2 xy = __ldg(&reinterpret_cast<const float2*>(pts)[b * NPTS + p]);
        const int px = (int)floorf(xy.x * INV_STRIDE);
        const int py = (int)floorf(xy.y * INV_STRIDE);
        const bool valid = (px >= 0) & (py >= 0) & (px < MASK_N) & (py < MASK_N);
        const int bias = valid ? 0 : 30000;

        // dx: cols 4g..4g+3 of this quadrant -> 2 packed u16 pairs
        const int d0 = j_base + (g << 2) - px;
        const int d1 = d0 + 1, d2 = d0 + 2, d3 = d0 + 3;
        const unsigned int q0 = (unsigned int)(d0 * d0) | ((unsigned int)(d1 * d1) << 16);
        const unsigned int q1 = (unsigned int)(d2 * d2) | ((unsigned int)(d3 * d3) << 16);
        sdx[g * DX_STRIDE + p] = make_uint2(q0, q1);

        // dy: rows 4g..4g+3 of this quadrant, duplicated u16x2
        #pragma unroll
        for (int r = 0; r < 4; r++) {
            const int row = (g << 2) + r;
            const int d = i_base + row - py;
            const unsigned int v = (unsigned int)(d * d + bias);
            sdy[row * DY_STRIDE + p] = v | (v << 16);
        }
    }
    __syncthreads();

    // ---- per-thread: 1 row x 4 cols; 4 points per iter via LDS.128 ----
    const int il = tid >> 3;            // 0..31 local row
    const int cg = tid & 7;             // col group: cols 4*cg..4*cg+3

    unsigned int m01 = 0xFFFFFFFFu, m23 = 0xFFFFFFFFu;

    const unsigned int* dyp = &sdy[il * DY_STRIDE];
    const uint2*        dxp = &sdx[cg * DX_STRIDE];

    #pragma unroll
    for (int p4 = 0; p4 < NPTS; p4 += 4) {
        const uint4 dy4 = *reinterpret_cast<const uint4*>(dyp + p4);      // dy for pts p4..p4+3
        const uint4 dxa = *reinterpret_cast<const uint4*>(dxp + p4);      // dx for pts p4, p4+1
        const uint4 dxb = *reinterpret_cast<const uint4*>(dxp + p4 + 2);  // dx for pts p4+2, p4+3
        m01 = __viaddmin_u16x2(dy4.x, dxa.x, m01);
        m23 = __viaddmin_u16x2(dy4.x, dxa.y, m23);
        m01 = __viaddmin_u16x2(dy4.y, dxa.z, m01);
        m23 = __viaddmin_u16x2(dy4.y, dxa.w, m23);
        m01 = __viaddmin_u16x2(dy4.z, dxb.x, m01);
        m23 = __viaddmin_u16x2(dy4.z, dxb.y, m23);
        m01 = __viaddmin_u16x2(dy4.w, dxb.z, m01);
        m23 = __viaddmin_u16x2(dy4.w, dxb.w, m23);
    }

    // ---- one exp per pixel ----
    const float g0 = __expf((float)(m01 & 0xFFFFu) * -INV_2SIG2);
    const float g1 = __expf((float)(m01 >> 16)     * -INV_2SIG2);
    const float g2 = __expf((float)(m23 & 0xFFFFu) * -INV_2SIG2);
    const float g3 = __expf((float)(m23 >> 16)     * -INV_2SIG2);

    // ---- stores ----
    const int i = i_base + il;
    const int j = j_base + (cg << 2);
    const size_t base = (size_t)b * (MASK_N * MASK_N) + (size_t)i * MASK_N + j;

    *reinterpret_cast<float4*>(point_out + base) = make_float4(g0, g1, g2, g3);

    const bool inY = (i >= ymin_i) & (i < ymax_i);
    float4 bv;
    bv.x = (inY & (j + 0 >= xmin_i) & (j + 0 < xmax_i)) ? 1.f : 0.f;
    bv.y = (inY & (j + 1 >= xmin_i) & (j + 1 < xmax_i)) ? 1.f : 0.f;
    bv.z = (inY & (j + 2 >= xmin_i) & (j + 2 < xmax_i)) ? 1.f : 0.f;
    bv.w = (inY & (j + 3 >= xmin_i) & (j + 3 < xmax_i)) ? 1.f : 0.f;
    *reinterpret_cast<float4*>(bbox_out + base) = bv;
}

extern "C" void kernel_launch(void* const* d_in, const int* in_sizes, int n_in,
                              void* d_out, int out_size) {
    const float* boxes = (const float*)d_in[0];   // 256*4
    const float* pts   = (const float*)d_in[1];   // 256*32*2
    float* out = (float*)d_out;                   // 2 * 256*64*64
    const int B = in_sizes[0] / 4;                // 256
    float* bbox_out  = out;
    float* point_out = out + (size_t)B * MASK_N * MASK_N;
    dim3 grid(B, 4);
    zim_masks_kernel<<<grid, 256>>>(boxes, pts, bbox_out, point_out);
}